// round 4
// baseline (speedup 1.0000x reference)
#include <cuda_runtime.h>
#include <cuda_fp16.h>
#include <math.h>

// Cone-beam forward projection.
// Volume repacked to fp16, batch+z+x interleaved:
//   g_vol8[z][y][x] = 8 halves: (b0,b1) x (z0,z1) x (x0,x1)  -> one 16B cell.
// Per sample: 2 aligned LDG.128 (rows y0, y1). Trilinear done in half2
// (batch pair in lanes), fp32 accumulation. Branchless body for MLP.
// vol in: [B=2, Z=96, Y=96, X=96] fp32. out: [B=2, A=48, V=96, U=96] fp32.

#define NZ 96
#define NY 96
#define NX 96
#define NV 96
#define NU 96
#define NA 48
#define NS 96

#define DSO 500.0f
#define DSD 1000.0f
#define DDET 2.0f

#define STEP 1.7320508075688772f
#define T0   416.86156123669393f

#define VOL_N (NZ * NY * NX)     // 884736
#define SY NX                    // 96
#define SZ (NX * NY)             // 9216

__device__ uint4 g_vol8[VOL_N];  // 14.2 MB

static __device__ __forceinline__ unsigned h2u(__half2 h) {
    union { __half2 h; unsigned u; } cvt; cvt.h = h; return cvt.u;
}
static __device__ __forceinline__ __half2 u2h(unsigned u) {
    union { unsigned u; __half2 h; } cvt; cvt.u = u; return cvt.h;
}

__global__ void __launch_bounds__(256) prep_kernel(const float* __restrict__ vol) {
    int i = blockIdx.x * blockDim.x + threadIdx.x;
    if (i >= VOL_N) return;
    int z = i / SZ;
    int x = i % NX;
    int xp = (x < NX - 1) ? 1 : 0;     // x=95 cell never read by interp (x0<=94)
    int zp = (z < NZ - 1) ? SZ : 0;    // z=95 cell never read

    const float* b0 = vol;
    const float* b1 = vol + VOL_N;

    uint4 q;
    q.x = h2u(__floats2half2_rn(b0[i],           b1[i]));            // z0,x0
    q.y = h2u(__floats2half2_rn(b0[i + xp],      b1[i + xp]));       // z0,x1
    q.z = h2u(__floats2half2_rn(b0[i + zp],      b1[i + zp]));       // z1,x0
    q.w = h2u(__floats2half2_rn(b0[i + zp + xp], b1[i + zp + xp]));  // z1,x1
    g_vol8[i] = q;
}

__global__ void __launch_bounds__(256) fp_kernel(float* __restrict__ out) {
    int idx = blockIdx.x * blockDim.x + threadIdx.x;
    // 48 * 96 * 96 = 442368 threads; each serves both batches
    int u = idx % NU;
    int v = (idx / NU) % NV;
    int a = idx / (NU * NV);

    float theta = (float)a * (6.2831853071795864769f / (float)NA);
    float s = sinf(theta);
    float c = cosf(theta);

    float srcx = DSO * c;
    float srcy = DSO * s;

    float uu = ((float)u - (NU - 1) * 0.5f) * DDET;
    float vv = ((float)v - (NV - 1) * 0.5f) * DDET;

    float px = -(DSD - DSO) * c - uu * s;
    float py = -(DSD - DSO) * s + uu * c;
    float pz = vv;

    float dx = px - srcx;
    float dy = py - srcy;
    float dz = pz;
    float inv = rsqrtf(fmaf(dx, dx, fmaf(dy, dy, dz * dz)));
    dx *= inv; dy *= inv; dz *= inv;

    // ray/box slab test, box = [-47.5, 47.5]^3 world
    const float H = 47.5f;
    float ix_ = 1.0f / dx, iy_ = 1.0f / dy, iz_ = 1.0f / dz;
    float tx1 = (-H - srcx) * ix_, tx2 = (H - srcx) * ix_;
    float ty1 = (-H - srcy) * iy_, ty2 = (H - srcy) * iy_;
    float tz1 = (-H) * iz_,        tz2 = (H) * iz_;
    float tmin = fmaxf(fmaxf(fminf(tx1, tx2), fminf(ty1, ty2)), fminf(tz1, tz2));
    float tmax = fminf(fminf(fmaxf(tx1, tx2), fmaxf(ty1, ty2)), fmaxf(tz1, tz2));

    int i0 = 0, i1 = 0;
    if (tmax > tmin) {
        i0 = max(0, (int)floorf((tmin - T0) / STEP - 0.5f) - 1);
        i1 = min(NS, (int)ceilf((tmax - T0) / STEP - 0.5f) + 2);
    }

    // shifted origin: voxel coord = src + d*t + 47.5
    float cx = srcx + (NX - 1) * 0.5f;
    float cy = srcy + (NY - 1) * 0.5f;
    float cz = (NZ - 1) * 0.5f;

    float acc0 = 0.0f, acc1 = 0.0f;

    #pragma unroll 8
    for (int i = i0; i < i1; i++) {
        float t = fmaf((float)i + 0.5f, STEP, T0);
        float x = fmaf(dx, t, cx);
        float y = fmaf(dy, t, cy);
        float z = fmaf(dz, t, cz);

        // validity mask (reference semantics), folded into accumulate
        float m = ((x >= 0.0f) & (x <= 95.0f) &
                   (y >= 0.0f) & (y <= 95.0f) &
                   (z >= 0.0f) & (z <= 95.0f)) ? 1.0f : 0.0f;

        // clip exactly like reference, then corner min
        float xc = fminf(fmaxf(x, 0.0f), 95.0f);
        float yc = fminf(fmaxf(y, 0.0f), 95.0f);
        float zc = fminf(fmaxf(z, 0.0f), 95.0f);
        int x0 = min((int)xc, NX - 2);
        int y0 = min((int)yc, NY - 2);
        int z0 = min((int)zc, NZ - 2);
        float fx = xc - (float)x0;
        float fy = yc - (float)y0;
        float fz = zc - (float)z0;

        const uint4* p = g_vol8 + (z0 * SZ + y0 * SY + x0);
        uint4 r0 = __ldg(p);        // row y0: (z0x0, z0x1, z1x0, z1x1) batch-pairs
        uint4 r1 = __ldg(p + SY);   // row y1

        // bilinear weights in (x,y), broadcast to half2
        float wd = fx * fy;
        float wb = fx - wd;
        float wc = fy - wd;
        float wa = 1.0f - fx - wc;
        __half2 wa2 = __float2half2_rn(wa);
        __half2 wb2 = __float2half2_rn(wb);
        __half2 wc2 = __float2half2_rn(wc);
        __half2 wd2 = __float2half2_rn(wd);
        __half2 fz2 = __float2half2_rn(fz);

        // z0 plane bilinear (batch0 = lane0, batch1 = lane1)
        __half2 p0 = __hmul2(u2h(r0.x), wa2);
        p0 = __hfma2(u2h(r0.y), wb2, p0);
        p0 = __hfma2(u2h(r1.x), wc2, p0);
        p0 = __hfma2(u2h(r1.y), wd2, p0);
        // z1 plane bilinear
        __half2 p1 = __hmul2(u2h(r0.z), wa2);
        p1 = __hfma2(u2h(r0.w), wb2, p1);
        p1 = __hfma2(u2h(r1.z), wc2, p1);
        p1 = __hfma2(u2h(r1.w), wd2, p1);

        // z lerp in half2, then convert once and accumulate in fp32
        __half2 pr = __hfma2(fz2, __hsub2(p1, p0), p0);
        float2 rf = __half22float2(pr);
        acc0 = fmaf(rf.x, m, acc0);
        acc1 = fmaf(rf.y, m, acc1);
    }

    out[idx] = acc0 * STEP;
    out[idx + NA * NV * NU] = acc1 * STEP;
}

extern "C" void kernel_launch(void* const* d_in, const int* in_sizes, int n_in,
                              void* d_out, int out_size) {
    const float* vol = (const float*)d_in[0];
    float* out = (float*)d_out;

    {
        int threads = 256;
        int blocks = (VOL_N + threads - 1) / threads;
        prep_kernel<<<blocks, threads>>>(vol);
    }
    {
        int total = NA * NV * NU;   // 442368
        int threads = 256;
        int blocks = (total + threads - 1) / threads;
        fp_kernel<<<blocks, threads>>>(out);
    }
}

// round 5
// speedup vs baseline: 1.0436x; 1.0436x over previous
#include <cuda_runtime.h>
#include <cuda_fp16.h>
#include <math.h>

// Cone-beam forward projection.
// Volume repacked to fp16, batch+z+x interleaved:
//   g_vol8[z][y][x] = 8 halves: (b0,b1) x (z0,z1) x (x0,x1)  -> one 16B cell.
// Per sample: 2 aligned LDG.128 (rows y0,y1). Two samples per loop iter with
// front-batched loads (MLP=4). fp32 interp + accumulation, mask folded in.
// vol in: [B=2, Z=96, Y=96, X=96] fp32. out: [B=2, A=48, V=96, U=96] fp32.

#define NZ 96
#define NY 96
#define NX 96
#define NV 96
#define NU 96
#define NA 48
#define NS 96

#define DSO 500.0f
#define DSD 1000.0f
#define DDET 2.0f

#define STEP 1.7320508075688772f
#define T0   416.86156123669393f

#define VOL_N (NZ * NY * NX)     // 884736
#define SY NX                    // 96
#define SZ (NX * NY)             // 9216

__device__ uint4 g_vol8[VOL_N];  // 14.2 MB

static __device__ __forceinline__ unsigned h2u(__half2 h) {
    union { __half2 h; unsigned u; } cvt; cvt.h = h; return cvt.u;
}
static __device__ __forceinline__ __half2 u2h(unsigned u) {
    union { unsigned u; __half2 h; } cvt; cvt.u = u; return cvt.h;
}

__global__ void __launch_bounds__(256) prep_kernel(const float* __restrict__ vol) {
    int i = blockIdx.x * blockDim.x + threadIdx.x;
    if (i >= VOL_N) return;
    int z = i / SZ;
    int x = i % NX;
    int xp = (x < NX - 1) ? 1 : 0;     // x=95 cell never read by interp (x0<=94)
    int zp = (z < NZ - 1) ? SZ : 0;    // z=95 cell never read

    const float* b0 = vol;
    const float* b1 = vol + VOL_N;

    uint4 q;
    q.x = h2u(__floats2half2_rn(b0[i],           b1[i]));            // z0,x0
    q.y = h2u(__floats2half2_rn(b0[i + xp],      b1[i + xp]));       // z0,x1
    q.z = h2u(__floats2half2_rn(b0[i + zp],      b1[i + zp]));       // z1,x0
    q.w = h2u(__floats2half2_rn(b0[i + zp + xp], b1[i + zp + xp]));  // z1,x1
    g_vol8[i] = q;
}

struct Samp {
    int off;        // cell offset
    float fx, fy, fz, m;
};

static __device__ __forceinline__ Samp make_samp(float t, float dx, float dy, float dz,
                                                 float cx, float cy, float cz) {
    float x = fmaf(dx, t, cx);
    float y = fmaf(dy, t, cy);
    float z = fmaf(dz, t, cz);
    Samp sp;
    sp.m = ((x >= 0.0f) & (x <= 95.0f) &
            (y >= 0.0f) & (y <= 95.0f) &
            (z >= 0.0f) & (z <= 95.0f)) ? 1.0f : 0.0f;
    float xc = fminf(fmaxf(x, 0.0f), 95.0f);
    float yc = fminf(fmaxf(y, 0.0f), 95.0f);
    float zc = fminf(fmaxf(z, 0.0f), 95.0f);
    int x0 = min((int)xc, NX - 2);
    int y0 = min((int)yc, NY - 2);
    int z0 = min((int)zc, NZ - 2);
    sp.fx = xc - (float)x0;
    sp.fy = yc - (float)y0;
    sp.fz = zc - (float)z0;
    sp.off = z0 * SZ + y0 * SY + x0;
    return sp;
}

// fp32 bilinear+z-lerp on one sample's two rows, accumulate with mask.
static __device__ __forceinline__ void interp_acc(const Samp& sp, uint4 r0, uint4 r1,
                                                  float& acc0, float& acc1) {
    float wd = sp.fx * sp.fy;
    float wb = sp.fx - wd;
    float wc = sp.fy - wd;
    float wa = 1.0f - sp.fx - wc;

    float2 a0 = __half22float2(u2h(r0.x));   // y0 z0 x0 (b0,b1)
    float2 a1 = __half22float2(u2h(r0.y));   // y0 z0 x1
    float2 a2 = __half22float2(u2h(r0.z));   // y0 z1 x0
    float2 a3 = __half22float2(u2h(r0.w));   // y0 z1 x1
    float2 c0 = __half22float2(u2h(r1.x));   // y1 z0 x0
    float2 c1 = __half22float2(u2h(r1.y));   // y1 z0 x1
    float2 c2 = __half22float2(u2h(r1.z));   // y1 z1 x0
    float2 c3 = __half22float2(u2h(r1.w));   // y1 z1 x1

    float p0x = fmaf(a0.x, wa, fmaf(a1.x, wb, fmaf(c0.x, wc, c1.x * wd)));
    float p0y = fmaf(a0.y, wa, fmaf(a1.y, wb, fmaf(c0.y, wc, c1.y * wd)));
    float p1x = fmaf(a2.x, wa, fmaf(a3.x, wb, fmaf(c2.x, wc, c3.x * wd)));
    float p1y = fmaf(a2.y, wa, fmaf(a3.y, wb, fmaf(c2.y, wc, c3.y * wd)));

    float rx = fmaf(sp.fz, p1x - p0x, p0x);
    float ry = fmaf(sp.fz, p1y - p0y, p0y);
    acc0 = fmaf(rx, sp.m, acc0);
    acc1 = fmaf(ry, sp.m, acc1);
}

__global__ void __launch_bounds__(256) fp_kernel(float* __restrict__ out) {
    int idx = blockIdx.x * blockDim.x + threadIdx.x;
    int u = idx % NU;
    int v = (idx / NU) % NV;
    int a = idx / (NU * NV);

    float theta = (float)a * (6.2831853071795864769f / (float)NA);
    float s = sinf(theta);
    float c = cosf(theta);

    float srcx = DSO * c;
    float srcy = DSO * s;

    float uu = ((float)u - (NU - 1) * 0.5f) * DDET;
    float vv = ((float)v - (NV - 1) * 0.5f) * DDET;

    float px = -(DSD - DSO) * c - uu * s;
    float py = -(DSD - DSO) * s + uu * c;
    float pz = vv;

    float dx = px - srcx;
    float dy = py - srcy;
    float dz = pz;
    float inv = rsqrtf(fmaf(dx, dx, fmaf(dy, dy, dz * dz)));
    dx *= inv; dy *= inv; dz *= inv;

    // ray/box slab test, box = [-47.5, 47.5]^3 world
    const float H = 47.5f;
    float ix_ = 1.0f / dx, iy_ = 1.0f / dy, iz_ = 1.0f / dz;
    float tx1 = (-H - srcx) * ix_, tx2 = (H - srcx) * ix_;
    float ty1 = (-H - srcy) * iy_, ty2 = (H - srcy) * iy_;
    float tz1 = (-H) * iz_,        tz2 = (H) * iz_;
    float tmin = fmaxf(fmaxf(fminf(tx1, tx2), fminf(ty1, ty2)), fminf(tz1, tz2));
    float tmax = fminf(fminf(fmaxf(tx1, tx2), fmaxf(ty1, ty2)), fmaxf(tz1, tz2));

    int i0 = 0, i1 = 0;
    if (tmax > tmin) {
        i0 = max(0, (int)floorf((tmin - T0) / STEP - 0.5f) - 1);
        i1 = min(NS, (int)ceilf((tmax - T0) / STEP - 0.5f) + 2);
    }

    float cx = srcx + (NX - 1) * 0.5f;
    float cy = srcy + (NY - 1) * 0.5f;
    float cz = (NZ - 1) * 0.5f;

    float acc0 = 0.0f, acc1 = 0.0f;

    const uint4* __restrict__ g = g_vol8;

    int i = i0;
    // two samples per iteration, loads front-batched
    for (; i + 1 < i1; i += 2) {
        float ta = fmaf((float)i + 0.5f, STEP, T0);
        float tb = fmaf((float)i + 1.5f, STEP, T0);
        Samp sa = make_samp(ta, dx, dy, dz, cx, cy, cz);
        Samp sb = make_samp(tb, dx, dy, dz, cx, cy, cz);

        uint4 ra0 = __ldg(g + sa.off);
        uint4 ra1 = __ldg(g + sa.off + SY);
        uint4 rb0 = __ldg(g + sb.off);
        uint4 rb1 = __ldg(g + sb.off + SY);

        interp_acc(sa, ra0, ra1, acc0, acc1);
        interp_acc(sb, rb0, rb1, acc0, acc1);
    }
    if (i < i1) {
        float ta = fmaf((float)i + 0.5f, STEP, T0);
        Samp sa = make_samp(ta, dx, dy, dz, cx, cy, cz);
        uint4 ra0 = __ldg(g + sa.off);
        uint4 ra1 = __ldg(g + sa.off + SY);
        interp_acc(sa, ra0, ra1, acc0, acc1);
    }

    out[idx] = acc0 * STEP;
    out[idx + NA * NV * NU] = acc1 * STEP;
}

extern "C" void kernel_launch(void* const* d_in, const int* in_sizes, int n_in,
                              void* d_out, int out_size) {
    const float* vol = (const float*)d_in[0];
    float* out = (float*)d_out;

    {
        int threads = 256;
        int blocks = (VOL_N + threads - 1) / threads;
        prep_kernel<<<blocks, threads>>>(vol);
    }
    {
        int total = NA * NV * NU;   // 442368
        int threads = 256;
        int blocks = (total + threads - 1) / threads;
        fp_kernel<<<blocks, threads>>>(out);
    }
}

// round 6
// speedup vs baseline: 1.1226x; 1.0757x over previous
#include <cuda_runtime.h>
#include <cuda_fp16.h>
#include <math.h>

// Cone-beam forward projection, dual-layout fp16 packed volume.
//
// Layout A: g_volA[z][y][x], cell = 8 halves (b0,b1) x (z0,z1) x (x0,x1).
//   Used when warp lanes (consecutive u) vary mostly in x (|sin|>=|cos|).
// Layout B: g_volB[z][x][y], cell = 8 halves (b0,b1) x (z0,z1) x (y0,y1).
//   Used when lanes vary mostly in y. Axis roles swapped before the loop,
//   so the inner body is identical: 2 aligned LDG.128 per sample, lanes
//   contiguous along the fast axis for EVERY angle.
// vol in: [B=2, Z=96, Y=96, X=96] fp32. out: [B=2, A=48, V=96, U=96] fp32.

#define NZ 96
#define NY 96
#define NX 96
#define NV 96
#define NU 96
#define NA 48
#define NS 96

#define DSO 500.0f
#define DSD 1000.0f
#define DDET 2.0f

#define STEP 1.7320508075688772f
#define T0   416.86156123669393f

#define VOL_N (NZ * NY * NX)     // 884736
#define SROW 96                  // cells between slow-axis rows (both layouts)
#define SZ (NX * NY)             // 9216

__device__ uint4 g_volA[VOL_N];  // 14.2 MB
__device__ uint4 g_volB[VOL_N];  // 14.2 MB

static __device__ __forceinline__ unsigned h2u(__half2 h) {
    union { __half2 h; unsigned u; } cvt; cvt.h = h; return cvt.u;
}
static __device__ __forceinline__ __half2 u2h(unsigned u) {
    union { unsigned u; __half2 h; } cvt; cvt.u = u; return cvt.h;
}

__global__ void __launch_bounds__(256) prep_kernel(const float* __restrict__ vol) {
    int j = blockIdx.x * blockDim.x + threadIdx.x;
    if (j >= VOL_N) return;

    const float* b0 = vol;
    const float* b1 = vol + VOL_N;

    // ---- layout A: j = z*SZ + y*96 + x ; fast pair = x ----
    {
        int z = j / SZ;
        int x = j % NX;
        int xp = (x < NX - 1) ? 1 : 0;
        int zp = (z < NZ - 1) ? SZ : 0;
        uint4 q;
        q.x = h2u(__floats2half2_rn(b0[j],           b1[j]));
        q.y = h2u(__floats2half2_rn(b0[j + xp],      b1[j + xp]));
        q.z = h2u(__floats2half2_rn(b0[j + zp],      b1[j + zp]));
        q.w = h2u(__floats2half2_rn(b0[j + zp + xp], b1[j + zp + xp]));
        g_volA[j] = q;
    }

    // ---- layout B: j = z*SZ + x*96 + y ; fast pair = y ----
    {
        int z = j / SZ;
        int r = j % SZ;
        int x = r / NX;
        int y = r % NX;
        int i = z * SZ + y * NX + x;        // source voxel index (z,y,x)
        int yp = (y < NY - 1) ? NX : 0;     // y+1 in source
        int zp = (z < NZ - 1) ? SZ : 0;
        uint4 q;
        q.x = h2u(__floats2half2_rn(b0[i],           b1[i]));
        q.y = h2u(__floats2half2_rn(b0[i + yp],      b1[i + yp]));
        q.z = h2u(__floats2half2_rn(b0[i + zp],      b1[i + zp]));
        q.w = h2u(__floats2half2_rn(b0[i + zp + yp], b1[i + zp + yp]));
        g_volB[j] = q;
    }
}

__global__ void __launch_bounds__(256) fp_kernel(float* __restrict__ out) {
    int idx = blockIdx.x * blockDim.x + threadIdx.x;
    // 48 * 96 * 96 = 442368 threads; each serves both batches
    int u = idx % NU;
    int v = (idx / NU) % NV;
    int a = idx / (NU * NV);

    float theta = (float)a * (6.2831853071795864769f / (float)NA);
    float s = sinf(theta);
    float c = cosf(theta);

    float srcx = DSO * c;
    float srcy = DSO * s;

    float uu = ((float)u - (NU - 1) * 0.5f) * DDET;
    float vv = ((float)v - (NV - 1) * 0.5f) * DDET;

    float px = -(DSD - DSO) * c - uu * s;
    float py = -(DSD - DSO) * s + uu * c;
    float pz = vv;

    float dx = px - srcx;
    float dy = py - srcy;
    float dz = pz;
    float inv = rsqrtf(fmaf(dx, dx, fmaf(dy, dy, dz * dz)));
    dx *= inv; dy *= inv; dz *= inv;

    // ray/box slab test, box = [-47.5, 47.5]^3 world (symmetric in x/y)
    const float H = 47.5f;
    float ix_ = 1.0f / dx, iy_ = 1.0f / dy, iz_ = 1.0f / dz;
    float tx1 = (-H - srcx) * ix_, tx2 = (H - srcx) * ix_;
    float ty1 = (-H - srcy) * iy_, ty2 = (H - srcy) * iy_;
    float tz1 = (-H) * iz_,        tz2 = (H) * iz_;
    float tmin = fmaxf(fmaxf(fminf(tx1, tx2), fminf(ty1, ty2)), fminf(tz1, tz2));
    float tmax = fminf(fminf(fmaxf(tx1, tx2), fmaxf(ty1, ty2)), fmaxf(tz1, tz2));

    int i0 = 0, i1 = 0;
    if (tmax > tmin) {
        i0 = max(0, (int)floorf((tmin - T0) / STEP - 0.5f) - 1);
        i1 = min(NS, (int)ceilf((tmax - T0) / STEP - 0.5f) + 2);
    }

    // pick layout so the warp's lane-varying axis is the fast (packed) axis
    bool useA = fabsf(s) >= fabsf(c);
    const uint4* __restrict__ g = useA ? g_volA : g_volB;

    // axis swap: inside the loop, "x" is always the fast axis, "y" the slow
    float fdx = useA ? dx : dy;
    float fdy = useA ? dy : dx;
    float cx = (useA ? srcx : srcy) + 47.5f;
    float cy = (useA ? srcy : srcx) + 47.5f;
    float cz = 47.5f;

    float acc0 = 0.0f, acc1 = 0.0f;

    #pragma unroll 4
    for (int i = i0; i < i1; i++) {
        float t = fmaf((float)i + 0.5f, STEP, T0);
        float x = fmaf(fdx, t, cx);   // fast axis
        float y = fmaf(fdy, t, cy);   // slow axis
        float z = fmaf(dz, t, cz);

        bool valid = (x >= 0.0f) & (x <= 95.0f) &
                     (y >= 0.0f) & (y <= 95.0f) &
                     (z >= 0.0f) & (z <= 95.0f);
        if (valid) {
            int x0 = min((int)x, NX - 2);
            int y0 = min((int)y, NY - 2);
            int z0 = min((int)z, NZ - 2);
            float fx = x - (float)x0;
            float fy = y - (float)y0;
            float fz = z - (float)z0;

            const uint4* p = g + (z0 * SZ + y0 * SROW + x0);
            uint4 r0 = __ldg(p);          // slow row 0: (z0f0, z0f1, z1f0, z1f1)
            uint4 r1 = __ldg(p + SROW);   // slow row 1

            float wd = fx * fy;
            float wb = fx - wd;
            float wc = fy - wd;
            float wa = 1.0f - fx - wc;

            float2 a0 = __half22float2(u2h(r0.x));
            float2 a1 = __half22float2(u2h(r0.y));
            float2 a2 = __half22float2(u2h(r0.z));
            float2 a3 = __half22float2(u2h(r0.w));
            float2 c0_ = __half22float2(u2h(r1.x));
            float2 c1_ = __half22float2(u2h(r1.y));
            float2 c2_ = __half22float2(u2h(r1.z));
            float2 c3_ = __half22float2(u2h(r1.w));

            float p0x = fmaf(a0.x, wa, fmaf(a1.x, wb, fmaf(c0_.x, wc, c1_.x * wd)));
            float p0y = fmaf(a0.y, wa, fmaf(a1.y, wb, fmaf(c0_.y, wc, c1_.y * wd)));
            float p1x = fmaf(a2.x, wa, fmaf(a3.x, wb, fmaf(c2_.x, wc, c3_.x * wd)));
            float p1y = fmaf(a2.y, wa, fmaf(a3.y, wb, fmaf(c2_.y, wc, c3_.y * wd)));

            acc0 += fmaf(fz, p1x - p0x, p0x);
            acc1 += fmaf(fz, p1y - p0y, p0y);
        }
    }

    out[idx] = acc0 * STEP;
    out[idx + NA * NV * NU] = acc1 * STEP;
}

extern "C" void kernel_launch(void* const* d_in, const int* in_sizes, int n_in,
                              void* d_out, int out_size) {
    const float* vol = (const float*)d_in[0];
    float* out = (float*)d_out;

    {
        int threads = 256;
        int blocks = (VOL_N + threads - 1) / threads;
        prep_kernel<<<blocks, threads>>>(vol);
    }
    {
        int total = NA * NV * NU;   // 442368
        int threads = 256;
        int blocks = (total + threads - 1) / threads;
        fp_kernel<<<blocks, threads>>>(out);
    }
}

// round 7
// speedup vs baseline: 1.3937x; 1.2415x over previous
#include <cuda_runtime.h>
#include <cuda_fp16.h>
#include <math.h>

// Cone-beam forward projection, dual-layout fp16 packed volume.
//
// Layout A: g_volA[z][y][x], cell = 8 halves (b0,b1) x (z0,z1) x (x0,x1).
// Layout B: g_volB[z][x][y], cell = 8 halves (b0,b1) x (z0,z1) x (y0,y1).
// fp_kernel picks the layout whose fast axis matches the warp's lane-varying
// world axis, so every angle gets lane-contiguous 16B-cell gathers.
// Prep: single smem-tiled pass builds BOTH layouts with coalesced I/O.
// vol in: [B=2, Z=96, Y=96, X=96] fp32. out: [B=2, A=48, V=96, U=96] fp32.

#define NZ 96
#define NY 96
#define NX 96
#define NV 96
#define NU 96
#define NA 48
#define NS 96

#define DSO 500.0f
#define DSD 1000.0f
#define DDET 2.0f

#define STEP 1.7320508075688772f
#define T0   416.86156123669393f

#define VOL_N (NZ * NY * NX)     // 884736
#define SROW 96
#define SZ (NX * NY)             // 9216

__device__ uint4 g_volA[VOL_N];  // 14.2 MB
__device__ uint4 g_volB[VOL_N];  // 14.2 MB

static __device__ __forceinline__ unsigned h2u(__half2 h) {
    union { __half2 h; unsigned u; } cvt; cvt.h = h; return cvt.u;
}
static __device__ __forceinline__ __half2 u2h(unsigned u) {
    union { unsigned u; __half2 h; } cvt; cvt.u = u; return cvt.h;
}

// ---------------------------------------------------------------------------
// Tiled prep: block handles a 32x32 (y,x) tile at one z. Stages clamped
// 33x33 neighborhoods of (b0,b1) half2 for planes z and z+1 in smem, then
// writes both layouts coalesced.
// grid = (NX/32, NY/32, NZ), block = 256.
// ---------------------------------------------------------------------------
__global__ void __launch_bounds__(256) prep_tiled(const float* __restrict__ vol) {
    __shared__ unsigned s0[33][34];   // plane z   : (b0,b1) packed; pad to 34
    __shared__ unsigned s1[33][34];   // plane z+1

    int x0t = blockIdx.x * 32;
    int y0t = blockIdx.y * 32;
    int z   = blockIdx.z;
    int zp  = min(z + 1, NZ - 1);

    const float* b0 = vol;
    const float* b1 = vol + VOL_N;

    int tid = threadIdx.x;   // 0..255

    // load 33x33 clamped neighborhood
    for (int k = tid; k < 33 * 33; k += 256) {
        int yl = k / 33;
        int xl = k - yl * 33;
        int gy = min(y0t + yl, NY - 1);
        int gx = min(x0t + xl, NX - 1);
        int i  = z * SZ + gy * NX + gx;
        int ip = zp * SZ + gy * NX + gx;
        s0[yl][xl] = h2u(__floats2half2_rn(b0[i],  b1[i]));
        s1[yl][xl] = h2u(__floats2half2_rn(b0[ip], b1[ip]));
    }
    __syncthreads();

    int tx = tid & 31;        // fast lane
    int ty = tid >> 5;        // 0..7

    // layout A: g_volA[z][y][x], cell = (z0x0, z0x1, z1x0, z1x1); x fast
    for (int yr = ty; yr < 32; yr += 8) {
        uint4 q;
        q.x = s0[yr][tx];
        q.y = s0[yr][tx + 1];
        q.z = s1[yr][tx];
        q.w = s1[yr][tx + 1];
        g_volA[z * SZ + (y0t + yr) * NX + (x0t + tx)] = q;
    }

    // layout B: g_volB[z][x][y], cell = (z0y0, z0y1, z1y0, z1y1); y fast
    for (int xr = ty; xr < 32; xr += 8) {
        uint4 q;
        q.x = s0[tx][xr];
        q.y = s0[tx + 1][xr];
        q.z = s1[tx][xr];
        q.w = s1[tx + 1][xr];
        g_volB[z * SZ + (x0t + xr) * NY + (y0t + tx)] = q;
    }
}

__global__ void __launch_bounds__(256) fp_kernel(float* __restrict__ out) {
    int idx = blockIdx.x * blockDim.x + threadIdx.x;
    // 48 * 96 * 96 = 442368 threads; each serves both batches
    int u = idx % NU;
    int v = (idx / NU) % NV;
    int a = idx / (NU * NV);

    float theta = (float)a * (6.2831853071795864769f / (float)NA);
    float s = sinf(theta);
    float c = cosf(theta);

    float srcx = DSO * c;
    float srcy = DSO * s;

    float uu = ((float)u - (NU - 1) * 0.5f) * DDET;
    float vv = ((float)v - (NV - 1) * 0.5f) * DDET;

    float px = -(DSD - DSO) * c - uu * s;
    float py = -(DSD - DSO) * s + uu * c;
    float pz = vv;

    float dx = px - srcx;
    float dy = py - srcy;
    float dz = pz;
    float inv = rsqrtf(fmaf(dx, dx, fmaf(dy, dy, dz * dz)));
    dx *= inv; dy *= inv; dz *= inv;

    // ray/box slab test, box = [-47.5, 47.5]^3 world (symmetric in x/y)
    const float H = 47.5f;
    float ix_ = 1.0f / dx, iy_ = 1.0f / dy, iz_ = 1.0f / dz;
    float tx1 = (-H - srcx) * ix_, tx2 = (H - srcx) * ix_;
    float ty1 = (-H - srcy) * iy_, ty2 = (H - srcy) * iy_;
    float tz1 = (-H) * iz_,        tz2 = (H) * iz_;
    float tmin = fmaxf(fmaxf(fminf(tx1, tx2), fminf(ty1, ty2)), fminf(tz1, tz2));
    float tmax = fminf(fminf(fmaxf(tx1, tx2), fmaxf(ty1, ty2)), fmaxf(tz1, tz2));

    int i0 = 0, i1 = 0;
    if (tmax > tmin) {
        i0 = max(0, (int)floorf((tmin - T0) / STEP - 0.5f) - 1);
        i1 = min(NS, (int)ceilf((tmax - T0) / STEP - 0.5f) + 2);
    }

    // pick layout so the warp's lane-varying axis is the fast (packed) axis
    bool useA = fabsf(s) >= fabsf(c);
    const uint4* __restrict__ g = useA ? g_volA : g_volB;

    // axis swap: inside the loop, "x" is always the fast axis, "y" the slow
    float fdx = useA ? dx : dy;
    float fdy = useA ? dy : dx;
    float cx = (useA ? srcx : srcy) + 47.5f;
    float cy = (useA ? srcy : srcx) + 47.5f;
    float cz = 47.5f;

    float acc0 = 0.0f, acc1 = 0.0f;

    #pragma unroll 4
    for (int i = i0; i < i1; i++) {
        float t = fmaf((float)i + 0.5f, STEP, T0);
        float x = fmaf(fdx, t, cx);   // fast axis
        float y = fmaf(fdy, t, cy);   // slow axis
        float z = fmaf(dz, t, cz);

        bool valid = (x >= 0.0f) & (x <= 95.0f) &
                     (y >= 0.0f) & (y <= 95.0f) &
                     (z >= 0.0f) & (z <= 95.0f);
        if (valid) {
            int x0 = min((int)x, NX - 2);
            int y0 = min((int)y, NY - 2);
            int z0 = min((int)z, NZ - 2);
            float fx = x - (float)x0;
            float fy = y - (float)y0;
            float fz = z - (float)z0;

            const uint4* p = g + (z0 * SZ + y0 * SROW + x0);
            uint4 r0 = __ldg(p);          // slow row 0: (z0f0, z0f1, z1f0, z1f1)
            uint4 r1 = __ldg(p + SROW);   // slow row 1

            float wd = fx * fy;
            float wb = fx - wd;
            float wc = fy - wd;
            float wa = 1.0f - fx - wc;

            float2 a0 = __half22float2(u2h(r0.x));
            float2 a1 = __half22float2(u2h(r0.y));
            float2 a2 = __half22float2(u2h(r0.z));
            float2 a3 = __half22float2(u2h(r0.w));
            float2 c0_ = __half22float2(u2h(r1.x));
            float2 c1_ = __half22float2(u2h(r1.y));
            float2 c2_ = __half22float2(u2h(r1.z));
            float2 c3_ = __half22float2(u2h(r1.w));

            float p0x = fmaf(a0.x, wa, fmaf(a1.x, wb, fmaf(c0_.x, wc, c1_.x * wd)));
            float p0y = fmaf(a0.y, wa, fmaf(a1.y, wb, fmaf(c0_.y, wc, c1_.y * wd)));
            float p1x = fmaf(a2.x, wa, fmaf(a3.x, wb, fmaf(c2_.x, wc, c3_.x * wd)));
            float p1y = fmaf(a2.y, wa, fmaf(a3.y, wb, fmaf(c2_.y, wc, c3_.y * wd)));

            acc0 += fmaf(fz, p1x - p0x, p0x);
            acc1 += fmaf(fz, p1y - p0y, p0y);
        }
    }

    out[idx] = acc0 * STEP;
    out[idx + NA * NV * NU] = acc1 * STEP;
}

extern "C" void kernel_launch(void* const* d_in, const int* in_sizes, int n_in,
                              void* d_out, int out_size) {
    const float* vol = (const float*)d_in[0];
    float* out = (float*)d_out;

    {
        dim3 grid(NX / 32, NY / 32, NZ);   // (3,3,96)
        prep_tiled<<<grid, 256>>>(vol);
    }
    {
        int total = NA * NV * NU;   // 442368
        int threads = 256;
        int blocks = (total + threads - 1) / threads;
        fp_kernel<<<blocks, threads>>>(out);
    }
}